// round 10
// baseline (speedup 1.0000x reference)
#include <cuda_runtime.h>
#include <cstddef>

// RoiAlign: 4-level FPN, B=2, N=1000, C=256, POOL=7
// out[B, N, 7, 7, C] float32
//
// 1) sort_kernel: counting-sort ROI indices by (batch, level, morton(center)).
// 2) roi_align_kernel: grid=148 (1 CTA/SM), 1024 threads. Each CTA owns a
//    contiguous slice of the sorted list: exclusive L1 + spatially adjacent
//    consecutive ROIs -> L1 hits on shared pixels bypass the LTS cap.
//    Ping-pong SMEM setup buffers: one __syncthreads() per ROI.

#define POOL    7
#define C_CH    256
#define NPOS    (POOL * POOL)   // 49
#define NSM     148
#define NBUCKET 2048
#define MAXROI  4096

__device__ unsigned int g_order[MAXROI];

__device__ __forceinline__ unsigned morton8(unsigned y, unsigned x) {
    unsigned m = 0;
    #pragma unroll
    for (int i = 0; i < 4; i++) {
        m |= ((x >> i) & 1u) << (2 * i);
        m |= ((y >> i) & 1u) << (2 * i + 1);
    }
    return m;
}

__device__ __forceinline__ int level_of(float x1, float y1, float x2, float y2) {
    const float area  = (y2 - y1) * (x2 - x1);
    const float canon = 56.0f / 1024.0f + 1e-6f;
    const float lf = floorf(logf(sqrtf(area) / canon) / logf(2.0f));
    int lvl = 0;
    if (lf >= 3.0f)       lvl = 3;
    else if (lf >= 1.0f)  lvl = (int)lf;
    return lvl;
}

// ---------------- sort: single CTA counting sort over 2048 buckets ----------
__global__ __launch_bounds__(1024, 1)
void sort_kernel(const float* __restrict__ props, int BN, int N)
{
    __shared__ unsigned       cnt[NBUCKET];
    __shared__ unsigned short s_key[MAXROI];

    const int tid = threadIdx.x;

    for (int i = tid; i < NBUCKET; i += 1024) cnt[i] = 0;
    __syncthreads();

    for (int i = tid; i < BN; i += 1024) {
        const float4 box = reinterpret_cast<const float4*>(props)[i];
        const int lvl = level_of(box.x, box.y, box.z, box.w);
        const int b   = i / N;
        const float cx = 0.5f * (box.x + box.z);
        const float cy = 0.5f * (box.y + box.w);
        const unsigned txi = (unsigned)min(15, max(0, (int)(cx * 16.0f)));
        const unsigned tyi = (unsigned)min(15, max(0, (int)(cy * 16.0f)));
        const unsigned key = ((unsigned)(b & 1) << 10) | ((unsigned)lvl << 8)
                           | morton8(tyi, txi);
        s_key[i] = (unsigned short)key;
        atomicAdd(&cnt[key], 1u);
    }
    __syncthreads();

    // exclusive prefix sum over 2048 buckets: warp 0, 64 buckets per lane
    if (tid < 32) {
        const int base = tid * 64;
        unsigned sum = 0;
        for (int j = 0; j < 64; j++) sum += cnt[base + j];
        unsigned inc = sum;
        #pragma unroll
        for (int d = 1; d < 32; d <<= 1) {
            unsigned v = __shfl_up_sync(0xffffffffu, inc, d);
            if (tid >= d) inc += v;
        }
        unsigned run = inc - sum;   // lane-exclusive offset
        for (int j = 0; j < 64; j++) {
            const unsigned c = cnt[base + j];
            cnt[base + j] = run;
            run += c;
        }
    }
    __syncthreads();

    for (int i = tid; i < BN; i += 1024) {
        const unsigned pos = atomicAdd(&cnt[s_key[i]], 1u);
        g_order[pos] = (unsigned)i;
    }
}

// ---------------- main: 1 CTA/SM, 1024 thr, ping-pong setup -----------------
struct RoiMeta {
    const char* fbb;
    char*       out_roi;
};

__device__ __forceinline__ void setup_roi(
    int roi, int N,
    const float* f0, const float* f1, const float* f2, const float* f3,
    const float* props, float* out,
    int4* s_off, float2* s_w, int tid,
    RoiMeta& meta)
{
    const int b = roi / N;
    const float4 box = reinterpret_cast<const float4*>(props)[roi];
    const float x1 = box.x, y1 = box.y, x2 = box.z, y2 = box.w;

    const int lvl = level_of(x1, y1, x2, y2);
    const int H = 256 >> lvl;
    const int W = 256 >> lvl;
    const float* f = (lvl == 0) ? f0 : (lvl == 1) ? f1 : (lvl == 2) ? f2 : f3;
    meta.fbb     = (const char*)(f + (size_t)b * H * W * C_CH);
    meta.out_roi = (char*)(out + (size_t)roi * (NPOS * C_CH));

    if (tid < NPOS) {
        const int p  = tid;
        const int py = p / POOL;
        const int px = p - py * POOL;

        const float Hf = (float)H - 1.0f;
        const float Wf = (float)W - 1.0f;

        const float in_y = y1 * Hf + (float)py * ((y2 - y1) * Hf / (float)(POOL - 1));
        const float in_x = x1 * Wf + (float)px * ((x2 - x1) * Wf / (float)(POOL - 1));

        const float tyf = floorf(in_y);
        const float txf = floorf(in_x);

        const int tyi = (int)tyf;
        const int txi = (int)txf;
        const int yT = min(max(tyi,     0), H - 1);
        const int yB = min(max(tyi + 1, 0), H - 1);
        const int xL = min(max(txi,     0), W - 1);
        const int xR = min(max(txi + 1, 0), W - 1);

        const int rT = yT * W;
        const int rB = yB * W;
        int4 o;
        o.x = (rT + xL) << 10;   // tl (pixel stride = C*4 = 1024 B)
        o.y = (rT + xR) << 10;   // tr
        o.z = (rB + xL) << 10;   // bl
        o.w = (rB + xR) << 10;   // br
        s_off[p] = o;
        s_w[p] = make_float2(in_x - txf, in_y - tyf);
    }
}

__global__ __launch_bounds__(1024, 1)
void roi_align_kernel(const float* __restrict__ f0,
                      const float* __restrict__ f1,
                      const float* __restrict__ f2,
                      const float* __restrict__ f3,
                      const float* __restrict__ props,
                      float* __restrict__ out,
                      int BN, int N)
{
    __shared__ int4   s_off[2][NPOS];
    __shared__ float2 s_w[2][NPOS];

    const int tid   = threadIdx.x;
    const int c16   = (tid & 63) << 4;   // byte offset in channel dim
    const int pbase = tid >> 6;          // 0..15 position groups

    // even static partition of sorted list
    const int start = (int)(((long long)blockIdx.x       * BN) / gridDim.x);
    const int end   = (int)(((long long)(blockIdx.x + 1) * BN) / gridDim.x);
    if (start >= end) return;

    RoiMeta meta_cur, meta_nxt;

    // prologue: set up first ROI into buffer 0
    setup_roi((int)g_order[start], N, f0, f1, f2, f3, props, out,
              s_off[0], s_w[0], tid, meta_cur);
    __syncthreads();

    for (int r = start; r < end; ++r) {
        const int cur = (r - start) & 1;

        // overlap: stage next ROI's tables into the other buffer
        if (r + 1 < end) {
            setup_roi((int)g_order[r + 1], N, f0, f1, f2, f3, props, out,
                      s_off[cur ^ 1], s_w[cur ^ 1], tid, meta_nxt);
        }

        const char* fbb = meta_cur.fbb;
        char* out_roi   = meta_cur.out_roi + c16;

        // 16 position groups cover 49 positions (p = pbase, pbase+16, pbase+32[, 48])
        #pragma unroll 2
        for (int p = pbase; p < NPOS; p += 16) {
            const int4   o = s_off[cur][p];
            const float2 w = s_w[cur][p];
            const float lx = w.x, ly = w.y;

            const float4 tl = *reinterpret_cast<const float4*>(fbb + o.x + c16);
            const float4 tr = *reinterpret_cast<const float4*>(fbb + o.y + c16);
            const float4 bl = *reinterpret_cast<const float4*>(fbb + o.z + c16);
            const float4 br = *reinterpret_cast<const float4*>(fbb + o.w + c16);

            float4 res;
            {
                const float top = tl.x + (tr.x - tl.x) * lx;
                const float bot = bl.x + (br.x - bl.x) * lx;
                res.x = top + (bot - top) * ly;
            }
            {
                const float top = tl.y + (tr.y - tl.y) * lx;
                const float bot = bl.y + (br.y - bl.y) * lx;
                res.y = top + (bot - top) * ly;
            }
            {
                const float top = tl.z + (tr.z - tl.z) * lx;
                const float bot = bl.z + (br.z - bl.z) * lx;
                res.z = top + (bot - top) * ly;
            }
            {
                const float top = tl.w + (tr.w - tl.w) * lx;
                const float bot = bl.w + (br.w - bl.w) * lx;
                res.w = top + (bot - top) * ly;
            }

            *reinterpret_cast<float4*>(out_roi + (p << 10)) = res;
        }

        meta_cur = meta_nxt;
        __syncthreads();   // next buffer ready; current buffer free for reuse
    }
}

extern "C" void kernel_launch(void* const* d_in, const int* in_sizes, int n_in,
                              void* d_out, int out_size)
{
    const float* f0    = (const float*)d_in[0];
    const float* f1    = (const float*)d_in[1];
    const float* f2    = (const float*)d_in[2];
    const float* f3    = (const float*)d_in[3];
    const float* props = (const float*)d_in[4];
    float* out = (float*)d_out;

    const int BN = in_sizes[4] / 4;                     // B*N rois
    const int B  = in_sizes[0] / (256 * 256 * 256);     // batch from feat0
    const int N  = (B > 0) ? (BN / B) : BN;

    const int grid = (BN < NSM) ? BN : NSM;

    sort_kernel<<<1, 1024>>>(props, BN, N);
    roi_align_kernel<<<grid, 1024>>>(f0, f1, f2, f3, props, out, BN, N);
}

// round 11
// speedup vs baseline: 1.7418x; 1.7418x over previous
#include <cuda_runtime.h>
#include <cstddef>

// RoiAlign: 4-level FPN, B=2, N=1000, C=256, POOL=7
// out[B, N, 7, 7, C] float32
// Inputs: feat0 [2,256,256,256], feat1 [2,128,128,256],
//         feat2 [2,64,64,256],   feat3 [2,32,32,256],
//         proposals [2,1000,4]  (x1,y1,x2,y2 in [0,1])
//
// Champion config (R5): 1 CTA/ROI, 256 thr, hoisted SMEM offset/weight tables,
// lerp-form bilinear, unroll 2. Kernel sits on the chip LTS-bandwidth roofline
// (492 MB through L2 at ~6300 B/cyc): measured 39.4us kernel / 41.0us e2e.

#define POOL 7
#define C_CH 256
#define NPOS (POOL * POOL)   // 49

__global__ __launch_bounds__(256, 6)
void roi_align_kernel(const float* __restrict__ f0,
                      const float* __restrict__ f1,
                      const float* __restrict__ f2,
                      const float* __restrict__ f3,
                      const float* __restrict__ props,
                      float* __restrict__ out,
                      int N)
{
    const int roi = blockIdx.x;          // 0 .. B*N-1
    const int b   = roi / N;

    // box (uniform across block)
    const float4 box = reinterpret_cast<const float4*>(props)[roi];
    const float x1 = box.x, y1 = box.y, x2 = box.z, y2 = box.w;

    // ---- level selection (replicates reference fp32 math exactly) ----
    const float area  = (y2 - y1) * (x2 - x1);
    const float canon = 56.0f / 1024.0f + 1e-6f;
    const float lf = floorf(logf(sqrtf(area) / canon) / logf(2.0f));
    int lvl = 0;
    if (lf >= 3.0f)       lvl = 3;
    else if (lf >= 1.0f)  lvl = (int)lf;

    const int H = 256 >> lvl;
    const int W = 256 >> lvl;
    const float* f = (lvl == 0) ? f0 : (lvl == 1) ? f1 : (lvl == 2) ? f2 : f3;
    const char* fbb = (const char*)(f + (size_t)b * H * W * C_CH);

    // ---- per-position corner byte-offsets + weights, computed once ----
    __shared__ int4   s_off[NPOS];   // byte offsets of tl, tr, bl, br
    __shared__ float2 s_w[NPOS];     // (lx, ly)

    if (threadIdx.x < NPOS) {
        const int p  = threadIdx.x;
        const int py = p / POOL;
        const int px = p - py * POOL;

        const float Hf = (float)H - 1.0f;
        const float Wf = (float)W - 1.0f;

        const float in_y = y1 * Hf + (float)py * ((y2 - y1) * Hf / (float)(POOL - 1));
        const float in_x = x1 * Wf + (float)px * ((x2 - x1) * Wf / (float)(POOL - 1));

        const float tyf = floorf(in_y);
        const float txf = floorf(in_x);

        const int tyi = (int)tyf;
        const int txi = (int)txf;
        const int yT = min(max(tyi,     0), H - 1);
        const int yB = min(max(tyi + 1, 0), H - 1);
        const int xL = min(max(txi,     0), W - 1);
        const int xR = min(max(txi + 1, 0), W - 1);

        // row byte stride = W*C*4; pixel stride = C*4 = 1024 B
        const int rT = yT * W;
        const int rB = yB * W;
        int4 o;
        o.x = (rT + xL) << 10;   // tl
        o.y = (rT + xR) << 10;   // tr
        o.z = (rB + xL) << 10;   // bl
        o.w = (rB + xR) << 10;   // br
        s_off[p] = o;
        s_w[p] = make_float2(in_x - txf, in_y - tyf);
    }
    __syncthreads();

    // 64 float4 lanes cover C=256; 4 pool positions in flight
    const int c16 = (threadIdx.x & 63) << 4;     // byte offset in channel dim
    const int pbase = threadIdx.x >> 6;          // 0..3
    char* out_roi = (char*)(out + (size_t)roi * (NPOS * C_CH)) + c16;

    #pragma unroll 2
    for (int p = pbase; p < NPOS; p += 4) {
        const int4   o = s_off[p];
        const float2 w = s_w[p];
        const float lx = w.x, ly = w.y;

        const float4 tl = *reinterpret_cast<const float4*>(fbb + o.x + c16);
        const float4 tr = *reinterpret_cast<const float4*>(fbb + o.y + c16);
        const float4 bl = *reinterpret_cast<const float4*>(fbb + o.z + c16);
        const float4 br = *reinterpret_cast<const float4*>(fbb + o.w + c16);

        float4 res;
        {
            const float top = tl.x + (tr.x - tl.x) * lx;
            const float bot = bl.x + (br.x - bl.x) * lx;
            res.x = top + (bot - top) * ly;
        }
        {
            const float top = tl.y + (tr.y - tl.y) * lx;
            const float bot = bl.y + (br.y - bl.y) * lx;
            res.y = top + (bot - top) * ly;
        }
        {
            const float top = tl.z + (tr.z - tl.z) * lx;
            const float bot = bl.z + (br.z - bl.z) * lx;
            res.z = top + (bot - top) * ly;
        }
        {
            const float top = tl.w + (tr.w - tl.w) * lx;
            const float bot = bl.w + (br.w - bl.w) * lx;
            res.w = top + (bot - top) * ly;
        }

        *reinterpret_cast<float4*>(out_roi + (p << 10)) = res;
    }
}

extern "C" void kernel_launch(void* const* d_in, const int* in_sizes, int n_in,
                              void* d_out, int out_size)
{
    const float* f0    = (const float*)d_in[0];
    const float* f1    = (const float*)d_in[1];
    const float* f2    = (const float*)d_in[2];
    const float* f3    = (const float*)d_in[3];
    const float* props = (const float*)d_in[4];
    float* out = (float*)d_out;

    const int BN = in_sizes[4] / 4;                     // B*N rois
    const int B  = in_sizes[0] / (256 * 256 * 256);     // batch from feat0
    const int N  = (B > 0) ? (BN / B) : BN;

    roi_align_kernel<<<BN, 256>>>(f0, f1, f2, f3, props, out, N);
}